// round 1
// baseline (speedup 1.0000x reference)
#include <cuda_runtime.h>

// VAE forward, B = 4,000,000 rows.
// Inputs (metadata order): x[B,8], eps[B,4], w1[6,8], w21[4,6], w22[4,6], w3[6,4], w4[8,6]
// Output: concat(out[B,8], mu[B,4], logvar[B,4]) as float32.
//
// Purely HBM-bound: 112 B/row traffic, ~176 FMA + 16 MUFU per row.
// One thread per row; weights staged to shared (broadcast reads); float4 I/O.

#define NTHREADS 256

__device__ __forceinline__ float elu_f(float v) {
    return v > 0.0f ? v : (__expf(v) - 1.0f);
}

__global__ __launch_bounds__(NTHREADS)
void vae_kernel(const float4* __restrict__ x,    // B*2 float4
                const float4* __restrict__ eps,  // B   float4
                const float*  __restrict__ w1,   // 48
                const float*  __restrict__ w21,  // 24
                const float*  __restrict__ w22,  // 24
                const float*  __restrict__ w3,   // 24
                const float*  __restrict__ w4,   // 48
                float4* __restrict__ out,        // B*2 float4
                float4* __restrict__ mu_out,     // B   float4
                float4* __restrict__ lv_out,     // B   float4
                int B)
{
    __shared__ float sw1[48], sw21[24], sw22[24], sw3[24], sw4[48];
    const int t = threadIdx.x;
    if (t < 48) sw1[t] = w1[t];
    if (t < 24) sw21[t] = w21[t];
    if (t < 24) sw22[t] = w22[t];
    if (t < 24) sw3[t]  = w3[t];
    if (t < 48) sw4[t]  = w4[t];
    __syncthreads();

    const int i = blockIdx.x * NTHREADS + t;
    if (i >= B) return;

    // ---- load x row (2x float4, fully coalesced across warp) ----
    const float4 xa = x[2 * i];
    const float4 xb = x[2 * i + 1];
    float xv[8] = {xa.x, xa.y, xa.z, xa.w, xb.x, xb.y, xb.z, xb.w};

    // ---- encoder: h1 = elu(x @ w1.T), w1 is [6,8] row-major ----
    float h1[6];
#pragma unroll
    for (int j = 0; j < 6; j++) {
        float s = 0.0f;
#pragma unroll
        for (int k = 0; k < 8; k++) s = fmaf(xv[k], sw1[j * 8 + k], s);
        h1[j] = elu_f(s);
    }

    // ---- mu = h1 @ w21.T, logvar = h1 @ w22.T (both [4,6]) ----
    float mu[4], lv[4];
#pragma unroll
    for (int j = 0; j < 4; j++) {
        float sm = 0.0f, sl = 0.0f;
#pragma unroll
        for (int k = 0; k < 6; k++) {
            sm = fmaf(h1[k], sw21[j * 6 + k], sm);
            sl = fmaf(h1[k], sw22[j * 6 + k], sl);
        }
        mu[j] = sm;
        lv[j] = sl;
    }

    // ---- reparameterize: z = mu + eps * exp(0.5*logvar) ----
    const float4 e = eps[i];
    float ev[4] = {e.x, e.y, e.z, e.w};
    float z[4];
#pragma unroll
    for (int j = 0; j < 4; j++)
        z[j] = fmaf(ev[j], __expf(0.5f * lv[j]), mu[j]);

    // ---- decoder: h3 = elu(z @ w3.T), w3 is [6,4] ----
    float h3[6];
#pragma unroll
    for (int j = 0; j < 6; j++) {
        float s = 0.0f;
#pragma unroll
        for (int k = 0; k < 4; k++) s = fmaf(z[k], sw3[j * 4 + k], s);
        h3[j] = elu_f(s);
    }

    // ---- out = h3 @ w4.T, w4 is [8,6] ----
    float o[8];
#pragma unroll
    for (int j = 0; j < 8; j++) {
        float s = 0.0f;
#pragma unroll
        for (int k = 0; k < 6; k++) s = fmaf(h3[k], sw4[j * 6 + k], s);
        o[j] = s;
    }

    // ---- stores (all float4, fully coalesced) ----
    out[2 * i]     = make_float4(o[0], o[1], o[2], o[3]);
    out[2 * i + 1] = make_float4(o[4], o[5], o[6], o[7]);
    mu_out[i]      = make_float4(mu[0], mu[1], mu[2], mu[3]);
    lv_out[i]      = make_float4(lv[0], lv[1], lv[2], lv[3]);
}

extern "C" void kernel_launch(void* const* d_in, const int* in_sizes, int n_in,
                              void* d_out, int out_size)
{
    const float4* x   = (const float4*)d_in[0];
    const float4* eps = (const float4*)d_in[1];
    const float*  w1  = (const float*)d_in[2];
    const float*  w21 = (const float*)d_in[3];
    const float*  w22 = (const float*)d_in[4];
    const float*  w3  = (const float*)d_in[5];
    const float*  w4  = (const float*)d_in[6];

    const int B = in_sizes[0] / 8;   // x is [B,8]

    float* outf = (float*)d_out;
    float4* out    = (float4*)outf;                      // [B,8] = B*2 float4
    float4* mu_out = (float4*)(outf + (size_t)B * 8);    // [B,4] = B float4
    float4* lv_out = (float4*)(outf + (size_t)B * 12);   // [B,4] = B float4

    const int grid = (B + NTHREADS - 1) / NTHREADS;
    vae_kernel<<<grid, NTHREADS>>>(x, eps, w1, w21, w22, w3, w4,
                                   out, mu_out, lv_out, B);
}